// round 14
// baseline (speedup 1.0000x reference)
#include <cuda_runtime.h>
#include <cuda_bf16.h>
#include <math.h>

// ---------------------------------------------------------------------------
// RPN 3D loss, GB300 (sm_103a) — round 14: round-10 structure + deferred
// candidate emission in k_main's hot loop.
//
//  k_main  : grid 9216 x 128thr (many waves -> load-balanced; R13 showed a
//            1-wave grid eats ~2x CTA spread). Hot loop = IoU argmax + 1-bit
//            candidate flag; division/pack/atomicMax deferred to a post-loop
//            walk of the (rare) candidate mask.
//  k_fixup : grid 256 x 32thr, one block per (image,gt) — winner by ballot,
//            signed corrections (bit-identical recomputation).
//  k_final : separate grid=1 x 32thr launch, tiny body (throttle-tolerant):
//            reduce buckets, write scalar, re-zero state (self-restoring).
//
// Throttle rule (R7/R8/R13): single-active-CTA phases are issue-throttled
// ~x38 scaling with body size; fused serial tails lose to a separate tiny
// launch. Heavy work stays wide (grid >> 148*occ).
//
// gt_valid (jnp bool) arrives as int32.
// ---------------------------------------------------------------------------

#define FEAT_H 32
#define FEAT_W 110
#define NA 36
#define NB 8
#define NG 32
#define A_TOTAL (FEAT_H * FEAT_W * NA)   // 126720
#define STRIDEF 16.0f
#define NBUCKET 64

__device__ unsigned long long g_best[NB * NG];   // (iou_bits<<32)|(~anchor)
__device__ int g_assign_buf[NB * A_TOTAL];       // agt | fg<<8 | bg<<9 (pre-force)
__device__ double g_acc2[5 * NBUCKET];           // ce, n_act, n_fg, l2, l3

__device__ __forceinline__ float smooth_l1(float x) {
    float ax = fabsf(x);
    return ax < 1.0f ? 0.5f * ax * ax : ax - 0.5f;
}

// Single shared implementation: fix-up corrections rely on bitwise-identical
// recomputation of k_main contributions.
__device__ __forceinline__ void reg_loss(
    int a, int agt, int b,
    const float* __restrict__ b2, const float* __restrict__ b3,
    const float* __restrict__ gtb, const float* __restrict__ gt3,
    const float* __restrict__ anc, const float* __restrict__ mn,
    const float* __restrict__ sd, float& l2, float& l3)
{
    int na = a % NA;
    int hw = a / NA;
    int wc = hw % FEAT_W;
    int hr = hw / FEAT_W;
    const float* an = anc + na * 9;
    float sx = wc * STRIDEF, sy = hr * STRIDEF;
    float x1 = sx + __ldg(an + 0), y1 = sy + __ldg(an + 1);
    float x2 = sx + __ldg(an + 2), y2 = sy + __ldg(an + 3);
    float w  = x2 - x1 + 1.0f, h = y2 - y1 + 1.0f;
    float cx = x1 + 0.5f * w,  cy = y1 + 0.5f * h;

    const float* gb = gtb + (b * NG + agt) * 4;
    const float* g3 = gt3 + (b * NG + agt) * 7;
    float gx1 = __ldg(gb + 0), gy1 = __ldg(gb + 1);
    float gx2 = __ldg(gb + 2), gy2 = __ldg(gb + 3);
    float gw = gx2 - gx1 + 1.0f, gh = gy2 - gy1 + 1.0f;
    float gcx = gx1 + 0.5f * gw, gcy = gy1 + 0.5f * gh;

    float t2[4], t3[7];
    t2[0] = (gcx - cx) / w;
    t2[1] = (gcy - cy) / h;
    t2[2] = logf(gw / w);
    t2[3] = logf(gh / h);
    t3[0] = (__ldg(g3 + 0) - cx) / w;
    t3[1] = (__ldg(g3 + 1) - cy) / h;
    t3[2] = __ldg(g3 + 2) - __ldg(an + 4);
    t3[3] = logf(__ldg(g3 + 3) / __ldg(an + 5));
    t3[4] = logf(__ldg(g3 + 4) / __ldg(an + 6));
    t3[5] = logf(__ldg(g3 + 5) / __ldg(an + 7));
    t3[6] = __ldg(g3 + 6) - __ldg(an + 8);

    const float4 p2 = __ldg(reinterpret_cast<const float4*>(b2) + b * A_TOTAL + a);
    float p2a[4] = {p2.x, p2.y, p2.z, p2.w};
    l2 = 0.0f; l3 = 0.0f;
    #pragma unroll
    for (int i = 0; i < 4; ++i) {
        float tv = (t2[i] - __ldg(mn + i)) / __ldg(sd + i);
        l2 += smooth_l1(p2a[i] - tv);
    }
    const float* p3 = b3 + (size_t)(b * A_TOTAL + a) * 7;
    #pragma unroll
    for (int i = 0; i < 7; ++i) {
        float tv = (t3[i] - __ldg(mn + 4 + i)) / __ldg(sd + 4 + i);
        l3 += smooth_l1(__ldg(p3 + i) - tv);
    }
}

__device__ __forceinline__ float lse4(float4 c) {
    float m = fmaxf(fmaxf(c.x, c.y), fmaxf(c.z, c.w));
    float se = __expf(c.x - m) + __expf(c.y - m) + __expf(c.z - m) + __expf(c.w - m);
    return m + __logf(se);
}

__device__ __forceinline__ float sel4(float4 c, int lbl) {
    return (lbl == 0) ? c.x : (lbl == 1) ? c.y : (lbl == 2) ? c.z : c.w;
}

// ------------------------------- k_main ------------------------------------
__global__ __launch_bounds__(128) void k_main(
    const float* __restrict__ cls,       // [B,A,4]
    const float* __restrict__ b2,        // [B,A,4]
    const float* __restrict__ b3,        // [B,A,7]
    const float* __restrict__ gtb,       // [B,G,4]
    const float* __restrict__ gt3,       // [B,G,7]
    const int*   __restrict__ glbl,      // [B,G]
    const int*   __restrict__ gval,      // [B,G]
    const float* __restrict__ anc,       // [NA,9]
    const float* __restrict__ mn,        // [1,11]
    const float* __restrict__ sd)        // [1,11]
{
    __shared__ float4 s_g4[NG];          // {gx1, gx2+1, ag, ih}
    __shared__ int    s_gidx[NG];
    __shared__ int    s_cnt, s_any;
    __shared__ float  s_red[4][5];

    int b  = blockIdx.y;
    int na = blockIdx.x % NA;
    int hr = blockIdx.x / NA;
    int t  = threadIdx.x;

    const float* an = anc + na * 9;
    float ax1 = __ldg(an + 0), ay1 = __ldg(an + 1);
    float ax2 = __ldg(an + 2), ay2 = __ldg(an + 3);
    float sy  = hr * STRIDEF;
    float y1  = sy + ay1, y2p = sy + ay2 + 1.0f;
    float hgt = y2p - y1;

    if (t < 32) {                        // warp 0: gt preprocessing + compaction
        const float* gb = gtb + (b * NG + t) * 4;
        float gx1 = gb[0], gy1 = gb[1], gx2 = gb[2], gy2 = gb[3];
        int v = (gval[b * NG + t] != 0);
        float ih = fminf(y2p, gy2 + 1.0f) - fmaxf(y1, gy1);
        ih = fmaxf(ih, 0.0f);
        int act = v && (ih > 0.0f);
        unsigned mact = __ballot_sync(0xFFFFFFFFu, act);
        unsigned mval = __ballot_sync(0xFFFFFFFFu, v);
        if (act) {
            int pos = __popc(mact & ((1u << t) - 1u));
            s_g4[pos] = make_float4(gx1, gx2 + 1.0f,
                                    (gx2 - gx1 + 1.0f) * (gy2 - gy1 + 1.0f), ih);
            s_gidx[pos] = t;
        }
        if (t == 0) { s_cnt = __popc(mact); s_any = (mval != 0u); }
    }
    __syncthreads();

    int  valid_t = (t < FEAT_W);
    int  cnt = s_cnt;
    int  a = (hr * FEAT_W + t) * NA + na;

    float sx  = t * STRIDEF;
    float x1  = sx + ax1, x2p = sx + ax2 + 1.0f;
    float ar  = (x2p - x1) * hgt;

    float bestI = -1.0f, bestU = 1.0f;
    int bestJ = 0;
    unsigned cmask = 0u;                 // deferred candidate flags
    int gbase = b * NG;

    // hot loop: argmax + 1-bit candidate flag only (no div/atomic here)
    #pragma unroll 4
    for (int j = 0; j < cnt; ++j) {
        float4 q = s_g4[j];
        float iw = fmaxf(fminf(x2p, q.y) - fmaxf(x1, q.x), 0.0f);
        float inter = iw * q.w;
        float uni   = (ar + q.z) - inter;
        if (inter * bestU > bestI * uni) { bestI = inter; bestU = uni; bestJ = j; }
        if (inter >= 0.3489f * uni) cmask |= (1u << j);   // widened; exact test in k_fixup
    }

    int fg0 = 0, bgc = 0, agt = 0;
    float r_ce = 0.0f, r_l2 = 0.0f, r_l3 = 0.0f;
    if (valid_t) {
        // deferred candidate emission (rare)
        unsigned cm = cmask;
        while (cm) {
            int j = __ffs(cm) - 1;
            cm &= cm - 1;
            float4 q = s_g4[j];
            float iw = fmaxf(fminf(x2p, q.y) - fmaxf(x1, q.x), 0.0f);
            float inter = iw * q.w;
            float uni   = (ar + q.z) - inter;
            float iou = inter / uni;
            unsigned long long pk =
                (((unsigned long long)__float_as_uint(iou)) << 32) |
                (unsigned long long)(0xFFFFFFFFu - (unsigned)a);
            atomicMax(&g_best[gbase + s_gidx[j]], pk);
        }

        float q = bestI / bestU;                   // IEEE div, as reference
        fg0 = (cnt > 0) && (q >= 0.5f);
        bgc = (!fg0) && s_any;
        agt = (cnt > 0) ? s_gidx[bestJ] : 0;
        // only candidate-emitting anchors can be read by k_fixup
        if (cmask)
            g_assign_buf[b * A_TOTAL + a] = agt | (fg0 << 8) | (bgc << 9);

        if (fg0 | bgc) {
            const float4 c = __ldg(reinterpret_cast<const float4*>(cls) + b * A_TOTAL + a);
            int lbl = fg0 ? __ldg(&glbl[b * NG + agt]) : 0;
            r_ce = lse4(c) - sel4(c, lbl);
        }
        if (fg0)
            reg_loss(a, agt, b, b2, b3, gtb, gt3, anc, mn, sd, r_l2, r_l3);
    }

    // block reduce -> bucketed atomics
    unsigned ba_act = __ballot_sync(0xFFFFFFFFu, fg0 | bgc);
    unsigned ba_fg  = __ballot_sync(0xFFFFFFFFu, fg0);
    #pragma unroll
    for (int off = 16; off; off >>= 1)
        r_ce += __shfl_down_sync(0xFFFFFFFFu, r_ce, off);
    if (ba_fg) {
        #pragma unroll
        for (int off = 16; off; off >>= 1) {
            r_l2 += __shfl_down_sync(0xFFFFFFFFu, r_l2, off);
            r_l3 += __shfl_down_sync(0xFFFFFFFFu, r_l3, off);
        }
    }
    int wid = t >> 5, lane = t & 31;
    if (lane == 0) {
        s_red[wid][0] = r_ce;
        s_red[wid][1] = (float)__popc(ba_act);
        s_red[wid][2] = (float)__popc(ba_fg);
        s_red[wid][3] = r_l2;
        s_red[wid][4] = r_l3;
    }
    __syncthreads();
    if (t == 0) {
        float u0 = 0, u1 = 0, u2 = 0, u3 = 0, u4 = 0;
        #pragma unroll
        for (int wv = 0; wv < 4; ++wv) {
            u0 += s_red[wv][0]; u1 += s_red[wv][1]; u2 += s_red[wv][2];
            u3 += s_red[wv][3]; u4 += s_red[wv][4];
        }
        int bucket = (blockIdx.x + blockIdx.y * 8) & (NBUCKET - 1);
        atomicAdd(&g_acc2[0 * NBUCKET + bucket], (double)u0);
        atomicAdd(&g_acc2[1 * NBUCKET + bucket], (double)u1);
        atomicAdd(&g_acc2[2 * NBUCKET + bucket], (double)u2);
        if (u2 > 0.0f) {
            atomicAdd(&g_acc2[3 * NBUCKET + bucket], (double)u3);
            atomicAdd(&g_acc2[4 * NBUCKET + bucket], (double)u4);
        }
    }
}

// ------------------------------- k_fixup -----------------------------------
// One block per (image b, gt g). 256 blocks -> no single-CTA throttle.
__global__ __launch_bounds__(32) void k_fixup(
    const float* __restrict__ cls,
    const float* __restrict__ b2,
    const float* __restrict__ b3,
    const float* __restrict__ gtb,
    const float* __restrict__ gt3,
    const int*   __restrict__ glbl,
    const int*   __restrict__ gval,
    const float* __restrict__ anc,
    const float* __restrict__ mn,
    const float* __restrict__ sd)
{
    int blk = blockIdx.x;                // 0..255
    int b = blk >> 5, g = blk & 31;
    int l = threadIdx.x;                 // 32 lanes: lane l handles gt l of image b

    unsigned long long pk = g_best[b * NG + l];
    float iou = __uint_as_float((unsigned)(pk >> 32));
    unsigned ba = 0xFFFFFFFFu - (unsigned)(pk & 0xFFFFFFFFull);
    int forced = (gval[b * NG + l] != 0) && (iou >= 0.35f);

    unsigned my_ba   = __shfl_sync(0xFFFFFFFFu, ba, g);
    int      my_frc  = __shfl_sync(0xFFFFFFFFu, forced, g);
    // winner = forced and no higher g (same image) forces the same anchor
    unsigned same = __ballot_sync(0xFFFFFFFFu, forced && (ba == my_ba));
    int winner = my_frc && ((same >> (g + 1)) == 0u);
    if (!winner || l != 0) return;

    int aa = (int)my_ba;
    int pko   = g_assign_buf[b * A_TOTAL + aa];
    int fg_o  = (pko >> 8) & 1;
    int bg_o  = (pko >> 9) & 1;
    int agt_o = pko & 0xFF;

    const float4 c = __ldg(reinterpret_cast<const float4*>(cls) + b * A_TOTAL + aa);
    float lse = lse4(c);
    int lbl_n = __ldg(&glbl[b * NG + g]);
    int lbl_o = fg_o ? __ldg(&glbl[b * NG + agt_o]) : 0;
    float ce_n = lse - sel4(c, lbl_n);
    float ce_o = (fg_o | bg_o) ? (lse - sel4(c, lbl_o)) : 0.0f;
    double dc0 = (double)ce_n - (double)ce_o;
    double dc1 = (fg_o | bg_o) ? 0.0 : 1.0;
    double dc2 = fg_o ? 0.0 : 1.0;

    float l2n, l3n;
    reg_loss(aa, g, b, b2, b3, gtb, gt3, anc, mn, sd, l2n, l3n);
    double dc3 = l2n, dc4 = l3n;
    if (fg_o) {
        float l2o, l3o;
        reg_loss(aa, agt_o, b, b2, b3, gtb, gt3, anc, mn, sd, l2o, l3o);
        dc3 -= (double)l2o; dc4 -= (double)l3o;
    }

    int bucket = blk & (NBUCKET - 1);
    if (dc0 != 0.0) atomicAdd(&g_acc2[0 * NBUCKET + bucket], dc0);
    if (dc1 != 0.0) atomicAdd(&g_acc2[1 * NBUCKET + bucket], dc1);
    if (dc2 != 0.0) atomicAdd(&g_acc2[2 * NBUCKET + bucket], dc2);
    if (dc3 != 0.0) atomicAdd(&g_acc2[3 * NBUCKET + bucket], dc3);
    if (dc4 != 0.0) atomicAdd(&g_acc2[4 * NBUCKET + bucket], dc4);
}

// ------------------------------- k_final -----------------------------------
// grid=1 x 32 threads; body kept minimal (single-CTA issue throttle).
__global__ __launch_bounds__(32) void k_final(float* __restrict__ out) {
    int l = threadIdx.x;
    double v[5];
    #pragma unroll
    for (int i = 0; i < 5; ++i)
        v[i] = g_acc2[i * NBUCKET + l] + g_acc2[i * NBUCKET + 32 + l];
    #pragma unroll
    for (int i = 0; i < 5; ++i)
        #pragma unroll
        for (int off = 16; off; off >>= 1)
            v[i] += __shfl_down_sync(0xFFFFFFFFu, v[i], off);
    if (l == 0) {
        double nact = v[1] > 1.0 ? v[1] : 1.0;
        double nfg  = v[2] > 1.0 ? v[2] : 1.0;
        out[0] = (float)(v[0] / nact + v[3] / nfg + v[4] / nfg);
    }
    __syncwarp();
    // restore invariant: scratch zero at next kernel_launch entry
    #pragma unroll
    for (int k = l; k < NB * NG; k += 32) g_best[k] = 0ull;
    #pragma unroll
    for (int k = l; k < 5 * NBUCKET; k += 32) g_acc2[k] = 0.0;
}

extern "C" void kernel_launch(void* const* d_in, const int* in_sizes, int n_in,
                              void* d_out, int out_size) {
    const float* cls  = (const float*)d_in[0];
    const float* b2   = (const float*)d_in[1];
    const float* b3   = (const float*)d_in[2];
    const float* gtb  = (const float*)d_in[3];
    const float* gt3  = (const float*)d_in[4];
    const int*   glbl = (const int*)d_in[5];
    const int*   gval = (const int*)d_in[6];
    const float* anc  = (const float*)d_in[7];
    const float* mn   = (const float*)d_in[8];
    const float* sd   = (const float*)d_in[9];
    float* out = (float*)d_out;

    k_main<<<dim3(NA * FEAT_H, NB), 128>>>(cls, b2, b3, gtb, gt3, glbl, gval, anc, mn, sd);
    k_fixup<<<NB * NG, 32>>>(cls, b2, b3, gtb, gt3, glbl, gval, anc, mn, sd);
    k_final<<<1, 32>>>(out);
}

// round 15
// speedup vs baseline: 1.4055x; 1.4055x over previous
#include <cuda_runtime.h>
#include <cuda_bf16.h>
#include <math.h>

// ---------------------------------------------------------------------------
// RPN 3D loss, GB300 (sm_103a) — round 15: R10 kernel + dual argmax chains
//
//  k_main  : grid 9216 x 128thr (R10 structure — measured 36.3us). Inner loop
//            processes 2 GTs per iteration with independent argmax chains
//            (even/odd) to halve the FSEL->FMUL dependency spine and overlap
//            the LDS.128 latencies. Exact lowest-j merge post-loop.
//            Candidate emission: R10's in-loop predicated form (deferred
//            variant measured WORSE in R14).
//  k_fixup : grid 256 x 32thr — winner by ballot, signed corrections.
//  k_final : separate grid=1 x 32thr tiny launch (fusing it measured worse:
//            single-active-CTA issue throttle, R13).
//
// gt_valid (jnp bool) arrives as int32.
// ---------------------------------------------------------------------------

#define FEAT_H 32
#define FEAT_W 110
#define NA 36
#define NB 8
#define NG 32
#define A_TOTAL (FEAT_H * FEAT_W * NA)   // 126720
#define STRIDEF 16.0f
#define NBUCKET 64

__device__ unsigned long long g_best[NB * NG];   // (iou_bits<<32)|(~anchor)
__device__ int g_assign_buf[NB * A_TOTAL];       // agt | fg<<8 | bg<<9 (pre-force)
__device__ double g_acc2[5 * NBUCKET];           // ce, n_act, n_fg, l2, l3

__device__ __forceinline__ float smooth_l1(float x) {
    float ax = fabsf(x);
    return ax < 1.0f ? 0.5f * ax * ax : ax - 0.5f;
}

// Single shared implementation: fix-up corrections rely on bitwise-identical
// recomputation of k_main contributions.
__device__ __forceinline__ void reg_loss(
    int a, int agt, int b,
    const float* __restrict__ b2, const float* __restrict__ b3,
    const float* __restrict__ gtb, const float* __restrict__ gt3,
    const float* __restrict__ anc, const float* __restrict__ mn,
    const float* __restrict__ sd, float& l2, float& l3)
{
    int na = a % NA;
    int hw = a / NA;
    int wc = hw % FEAT_W;
    int hr = hw / FEAT_W;
    const float* an = anc + na * 9;
    float sx = wc * STRIDEF, sy = hr * STRIDEF;
    float x1 = sx + __ldg(an + 0), y1 = sy + __ldg(an + 1);
    float x2 = sx + __ldg(an + 2), y2 = sy + __ldg(an + 3);
    float w  = x2 - x1 + 1.0f, h = y2 - y1 + 1.0f;
    float cx = x1 + 0.5f * w,  cy = y1 + 0.5f * h;

    const float* gb = gtb + (b * NG + agt) * 4;
    const float* g3 = gt3 + (b * NG + agt) * 7;
    float gx1 = __ldg(gb + 0), gy1 = __ldg(gb + 1);
    float gx2 = __ldg(gb + 2), gy2 = __ldg(gb + 3);
    float gw = gx2 - gx1 + 1.0f, gh = gy2 - gy1 + 1.0f;
    float gcx = gx1 + 0.5f * gw, gcy = gy1 + 0.5f * gh;

    float t2[4], t3[7];
    t2[0] = (gcx - cx) / w;
    t2[1] = (gcy - cy) / h;
    t2[2] = logf(gw / w);
    t2[3] = logf(gh / h);
    t3[0] = (__ldg(g3 + 0) - cx) / w;
    t3[1] = (__ldg(g3 + 1) - cy) / h;
    t3[2] = __ldg(g3 + 2) - __ldg(an + 4);
    t3[3] = logf(__ldg(g3 + 3) / __ldg(an + 5));
    t3[4] = logf(__ldg(g3 + 4) / __ldg(an + 6));
    t3[5] = logf(__ldg(g3 + 5) / __ldg(an + 7));
    t3[6] = __ldg(g3 + 6) - __ldg(an + 8);

    const float4 p2 = __ldg(reinterpret_cast<const float4*>(b2) + b * A_TOTAL + a);
    float p2a[4] = {p2.x, p2.y, p2.z, p2.w};
    l2 = 0.0f; l3 = 0.0f;
    #pragma unroll
    for (int i = 0; i < 4; ++i) {
        float tv = (t2[i] - __ldg(mn + i)) / __ldg(sd + i);
        l2 += smooth_l1(p2a[i] - tv);
    }
    const float* p3 = b3 + (size_t)(b * A_TOTAL + a) * 7;
    #pragma unroll
    for (int i = 0; i < 7; ++i) {
        float tv = (t3[i] - __ldg(mn + 4 + i)) / __ldg(sd + 4 + i);
        l3 += smooth_l1(__ldg(p3 + i) - tv);
    }
}

__device__ __forceinline__ float lse4(float4 c) {
    float m = fmaxf(fmaxf(c.x, c.y), fmaxf(c.z, c.w));
    float se = __expf(c.x - m) + __expf(c.y - m) + __expf(c.z - m) + __expf(c.w - m);
    return m + __logf(se);
}

__device__ __forceinline__ float sel4(float4 c, int lbl) {
    return (lbl == 0) ? c.x : (lbl == 1) ? c.y : (lbl == 2) ? c.z : c.w;
}

// ------------------------------- k_main ------------------------------------
__global__ __launch_bounds__(128) void k_main(
    const float* __restrict__ cls,       // [B,A,4]
    const float* __restrict__ b2,        // [B,A,4]
    const float* __restrict__ b3,        // [B,A,7]
    const float* __restrict__ gtb,       // [B,G,4]
    const float* __restrict__ gt3,       // [B,G,7]
    const int*   __restrict__ glbl,      // [B,G]
    const int*   __restrict__ gval,      // [B,G]
    const float* __restrict__ anc,       // [NA,9]
    const float* __restrict__ mn,        // [1,11]
    const float* __restrict__ sd)        // [1,11]
{
    __shared__ float4 s_g4[NG];          // {gx1, gx2+1, ag, ih}
    __shared__ int    s_gidx[NG];
    __shared__ int    s_cnt, s_any;
    __shared__ float  s_red[4][5];

    int b  = blockIdx.y;
    int na = blockIdx.x % NA;
    int hr = blockIdx.x / NA;
    int t  = threadIdx.x;

    const float* an = anc + na * 9;
    float ax1 = __ldg(an + 0), ay1 = __ldg(an + 1);
    float ax2 = __ldg(an + 2), ay2 = __ldg(an + 3);
    float sy  = hr * STRIDEF;
    float y1  = sy + ay1, y2p = sy + ay2 + 1.0f;
    float hgt = y2p - y1;

    if (t < 32) {                        // warp 0: gt preprocessing + compaction
        const float* gb = gtb + (b * NG + t) * 4;
        float gx1 = gb[0], gy1 = gb[1], gx2 = gb[2], gy2 = gb[3];
        int v = (gval[b * NG + t] != 0);
        float ih = fminf(y2p, gy2 + 1.0f) - fmaxf(y1, gy1);
        ih = fmaxf(ih, 0.0f);
        int act = v && (ih > 0.0f);
        unsigned mact = __ballot_sync(0xFFFFFFFFu, act);
        unsigned mval = __ballot_sync(0xFFFFFFFFu, v);
        if (act) {
            int pos = __popc(mact & ((1u << t) - 1u));
            s_g4[pos] = make_float4(gx1, gx2 + 1.0f,
                                    (gx2 - gx1 + 1.0f) * (gy2 - gy1 + 1.0f), ih);
            s_gidx[pos] = t;
        }
        if (t == 0) { s_cnt = __popc(mact); s_any = (mval != 0u); }
    }
    __syncthreads();

    int  valid_t = (t < FEAT_W);
    int  cnt = s_cnt;
    int  a = (hr * FEAT_W + t) * NA + na;

    float sx  = t * STRIDEF;
    float x1  = sx + ax1, x2p = sx + ax2 + 1.0f;
    float ar  = (x2p - x1) * hgt;

    // two independent argmax chains (even/odd j): halves the serial
    // FSEL->FMUL dependency spine and overlaps the two LDS.128 latencies.
    float bI0 = -1.0f, bU0 = 1.0f;  int bJ0 = 0;
    float bI1 = -1.0f, bU1 = 1.0f;  int bJ1 = 0;
    int emitted = 0;
    int gbase = b * NG;

    int j = 0;
    for (; j + 1 < cnt; j += 2) {
        float4 q0 = s_g4[j];
        float4 q1 = s_g4[j + 1];
        float iw0 = fmaxf(fminf(x2p, q0.y) - fmaxf(x1, q0.x), 0.0f);
        float iw1 = fmaxf(fminf(x2p, q1.y) - fmaxf(x1, q1.x), 0.0f);
        float in0 = iw0 * q0.w;
        float in1 = iw1 * q1.w;
        float un0 = (ar + q0.z) - in0;
        float un1 = (ar + q1.z) - in1;
        if (in0 * bU0 > bI0 * un0) { bI0 = in0; bU0 = un0; bJ0 = j; }
        if (in1 * bU1 > bI1 * un1) { bI1 = in1; bU1 = un1; bJ1 = j + 1; }
        if (valid_t && in0 >= 0.3489f * un0) {     // widened; exact test in k_fixup
            float iou = in0 / un0;
            unsigned long long pk =
                (((unsigned long long)__float_as_uint(iou)) << 32) |
                (unsigned long long)(0xFFFFFFFFu - (unsigned)a);
            atomicMax(&g_best[gbase + s_gidx[j]], pk);
            emitted = 1;
        }
        if (valid_t && in1 >= 0.3489f * un1) {
            float iou = in1 / un1;
            unsigned long long pk =
                (((unsigned long long)__float_as_uint(iou)) << 32) |
                (unsigned long long)(0xFFFFFFFFu - (unsigned)a);
            atomicMax(&g_best[gbase + s_gidx[j + 1]], pk);
            emitted = 1;
        }
    }
    if (j < cnt) {                       // remainder -> chain 0 (real j kept)
        float4 q0 = s_g4[j];
        float iw0 = fmaxf(fminf(x2p, q0.y) - fmaxf(x1, q0.x), 0.0f);
        float in0 = iw0 * q0.w;
        float un0 = (ar + q0.z) - in0;
        if (in0 * bU0 > bI0 * un0) { bI0 = in0; bU0 = un0; bJ0 = j; }
        if (valid_t && in0 >= 0.3489f * un0) {
            float iou = in0 / un0;
            unsigned long long pk =
                (((unsigned long long)__float_as_uint(iou)) << 32) |
                (unsigned long long)(0xFFFFFFFFu - (unsigned)a);
            atomicMax(&g_best[gbase + s_gidx[j]], pk);
            emitted = 1;
        }
    }

    // exact merge, lowest-j-wins on rational tie (empty chain: I=-1 -> loses
    // to any real candidate since its cross-product is negative).
    float p0 = bI0 * bU1, p1 = bI1 * bU0;
    int pick1 = (p1 > p0) || (p1 == p0 && bJ1 < bJ0);
    float bestI = pick1 ? bI1 : bI0;
    float bestU = pick1 ? bU1 : bU0;
    int   bestJ = pick1 ? bJ1 : bJ0;

    int fg0 = 0, bgc = 0, agt = 0;
    float r_ce = 0.0f, r_l2 = 0.0f, r_l3 = 0.0f;
    if (valid_t) {
        float q = bestI / bestU;                   // IEEE div, as reference
        fg0 = (cnt > 0) && (q >= 0.5f);
        bgc = (!fg0) && s_any;
        agt = (cnt > 0) ? s_gidx[bestJ] : 0;
        // only candidate-emitting anchors can be read by k_fixup
        if (emitted)
            g_assign_buf[b * A_TOTAL + a] = agt | (fg0 << 8) | (bgc << 9);

        if (fg0 | bgc) {
            const float4 c = __ldg(reinterpret_cast<const float4*>(cls) + b * A_TOTAL + a);
            int lbl = fg0 ? __ldg(&glbl[b * NG + agt]) : 0;
            r_ce = lse4(c) - sel4(c, lbl);
        }
        if (fg0)
            reg_loss(a, agt, b, b2, b3, gtb, gt3, anc, mn, sd, r_l2, r_l3);
    }

    // block reduce -> bucketed atomics
    unsigned ba_act = __ballot_sync(0xFFFFFFFFu, fg0 | bgc);
    unsigned ba_fg  = __ballot_sync(0xFFFFFFFFu, fg0);
    #pragma unroll
    for (int off = 16; off; off >>= 1)
        r_ce += __shfl_down_sync(0xFFFFFFFFu, r_ce, off);
    if (ba_fg) {
        #pragma unroll
        for (int off = 16; off; off >>= 1) {
            r_l2 += __shfl_down_sync(0xFFFFFFFFu, r_l2, off);
            r_l3 += __shfl_down_sync(0xFFFFFFFFu, r_l3, off);
        }
    }
    int wid = t >> 5, lane = t & 31;
    if (lane == 0) {
        s_red[wid][0] = r_ce;
        s_red[wid][1] = (float)__popc(ba_act);
        s_red[wid][2] = (float)__popc(ba_fg);
        s_red[wid][3] = r_l2;
        s_red[wid][4] = r_l3;
    }
    __syncthreads();
    if (t == 0) {
        float u0 = 0, u1 = 0, u2 = 0, u3 = 0, u4 = 0;
        #pragma unroll
        for (int wv = 0; wv < 4; ++wv) {
            u0 += s_red[wv][0]; u1 += s_red[wv][1]; u2 += s_red[wv][2];
            u3 += s_red[wv][3]; u4 += s_red[wv][4];
        }
        int bucket = (blockIdx.x + blockIdx.y * 8) & (NBUCKET - 1);
        atomicAdd(&g_acc2[0 * NBUCKET + bucket], (double)u0);
        atomicAdd(&g_acc2[1 * NBUCKET + bucket], (double)u1);
        atomicAdd(&g_acc2[2 * NBUCKET + bucket], (double)u2);
        if (u2 > 0.0f) {
            atomicAdd(&g_acc2[3 * NBUCKET + bucket], (double)u3);
            atomicAdd(&g_acc2[4 * NBUCKET + bucket], (double)u4);
        }
    }
}

// ------------------------------- k_fixup -----------------------------------
// One block per (image b, gt g). 256 blocks -> no single-CTA throttle.
__global__ __launch_bounds__(32) void k_fixup(
    const float* __restrict__ cls,
    const float* __restrict__ b2,
    const float* __restrict__ b3,
    const float* __restrict__ gtb,
    const float* __restrict__ gt3,
    const int*   __restrict__ glbl,
    const int*   __restrict__ gval,
    const float* __restrict__ anc,
    const float* __restrict__ mn,
    const float* __restrict__ sd)
{
    int blk = blockIdx.x;                // 0..255
    int b = blk >> 5, g = blk & 31;
    int l = threadIdx.x;                 // 32 lanes: lane l handles gt l of image b

    unsigned long long pk = g_best[b * NG + l];
    float iou = __uint_as_float((unsigned)(pk >> 32));
    unsigned ba = 0xFFFFFFFFu - (unsigned)(pk & 0xFFFFFFFFull);
    int forced = (gval[b * NG + l] != 0) && (iou >= 0.35f);

    unsigned my_ba   = __shfl_sync(0xFFFFFFFFu, ba, g);
    int      my_frc  = __shfl_sync(0xFFFFFFFFu, forced, g);
    // winner = forced and no higher g (same image) forces the same anchor
    unsigned same = __ballot_sync(0xFFFFFFFFu, forced && (ba == my_ba));
    int winner = my_frc && ((same >> (g + 1)) == 0u);
    if (!winner || l != 0) return;

    int aa = (int)my_ba;
    int pko   = g_assign_buf[b * A_TOTAL + aa];
    int fg_o  = (pko >> 8) & 1;
    int bg_o  = (pko >> 9) & 1;
    int agt_o = pko & 0xFF;

    const float4 c = __ldg(reinterpret_cast<const float4*>(cls) + b * A_TOTAL + aa);
    float lse = lse4(c);
    int lbl_n = __ldg(&glbl[b * NG + g]);
    int lbl_o = fg_o ? __ldg(&glbl[b * NG + agt_o]) : 0;
    float ce_n = lse - sel4(c, lbl_n);
    float ce_o = (fg_o | bg_o) ? (lse - sel4(c, lbl_o)) : 0.0f;
    double dc0 = (double)ce_n - (double)ce_o;
    double dc1 = (fg_o | bg_o) ? 0.0 : 1.0;
    double dc2 = fg_o ? 0.0 : 1.0;

    float l2n, l3n;
    reg_loss(aa, g, b, b2, b3, gtb, gt3, anc, mn, sd, l2n, l3n);
    double dc3 = l2n, dc4 = l3n;
    if (fg_o) {
        float l2o, l3o;
        reg_loss(aa, agt_o, b, b2, b3, gtb, gt3, anc, mn, sd, l2o, l3o);
        dc3 -= (double)l2o; dc4 -= (double)l3o;
    }

    int bucket = blk & (NBUCKET - 1);
    if (dc0 != 0.0) atomicAdd(&g_acc2[0 * NBUCKET + bucket], dc0);
    if (dc1 != 0.0) atomicAdd(&g_acc2[1 * NBUCKET + bucket], dc1);
    if (dc2 != 0.0) atomicAdd(&g_acc2[2 * NBUCKET + bucket], dc2);
    if (dc3 != 0.0) atomicAdd(&g_acc2[3 * NBUCKET + bucket], dc3);
    if (dc4 != 0.0) atomicAdd(&g_acc2[4 * NBUCKET + bucket], dc4);
}

// ------------------------------- k_final -----------------------------------
// grid=1 x 32 threads; body kept minimal (single-CTA issue throttle).
__global__ __launch_bounds__(32) void k_final(float* __restrict__ out) {
    int l = threadIdx.x;
    double v[5];
    #pragma unroll
    for (int i = 0; i < 5; ++i)
        v[i] = g_acc2[i * NBUCKET + l] + g_acc2[i * NBUCKET + 32 + l];
    #pragma unroll
    for (int i = 0; i < 5; ++i)
        #pragma unroll
        for (int off = 16; off; off >>= 1)
            v[i] += __shfl_down_sync(0xFFFFFFFFu, v[i], off);
    if (l == 0) {
        double nact = v[1] > 1.0 ? v[1] : 1.0;
        double nfg  = v[2] > 1.0 ? v[2] : 1.0;
        out[0] = (float)(v[0] / nact + v[3] / nfg + v[4] / nfg);
    }
    __syncwarp();
    // restore invariant: scratch zero at next kernel_launch entry
    #pragma unroll
    for (int k = l; k < NB * NG; k += 32) g_best[k] = 0ull;
    #pragma unroll
    for (int k = l; k < 5 * NBUCKET; k += 32) g_acc2[k] = 0.0;
}

extern "C" void kernel_launch(void* const* d_in, const int* in_sizes, int n_in,
                              void* d_out, int out_size) {
    const float* cls  = (const float*)d_in[0];
    const float* b2   = (const float*)d_in[1];
    const float* b3   = (const float*)d_in[2];
    const float* gtb  = (const float*)d_in[3];
    const float* gt3  = (const float*)d_in[4];
    const int*   glbl = (const int*)d_in[5];
    const int*   gval = (const int*)d_in[6];
    const float* anc  = (const float*)d_in[7];
    const float* mn   = (const float*)d_in[8];
    const float* sd   = (const float*)d_in[9];
    float* out = (float*)d_out;

    k_main<<<dim3(NA * FEAT_H, NB), 128>>>(cls, b2, b3, gtb, gt3, glbl, gval, anc, mn, sd);
    k_fixup<<<NB * NG, 32>>>(cls, b2, b3, gtb, gt3, glbl, gval, anc, mn, sd);
    k_final<<<1, 32>>>(out);
}